// round 8
// baseline (speedup 1.0000x reference)
#include <cuda_runtime.h>
#include <cuda_bf16.h>
#include <cstdint>

#define NN 100000
#define NE 1600000
#define FH 128
#define FO 40

// ======================= device scratch (no allocs allowed) =======================
__device__ int   g_deg[NN];
__device__ float g_dinv[NN];
__device__ float g_rdinv[NN];
__device__ int   g_rowoff[NN + 1];
__device__ int   g_cursor[NN];
__device__ int   g_csr[NE];
__device__ int   g_bsum[128];
__device__ int   g_boff[128];

// biased-int16 row-quantized prescaled activation planes: x*dinv ~= s_row*(q'-32768)
__device__ unsigned short g_I0[2][(size_t)NN * FH];
__device__ float g_S0[2][NN];
__device__ unsigned short g_I1[(size_t)NN * FH];
__device__ float g_S1[NN];
__device__ unsigned short g_I2[(size_t)NN * FH];
__device__ float g_S2[NN];
// weights (exact hi/lo bf16 split)
__device__ __nv_bfloat16 g_Wth[6 * 128 * 384];   // W^T per layer: [n=128][k=384], hi
__device__ __nv_bfloat16 g_Wtl[6 * 128 * 384];   // lo

// ======================= helpers =======================
__device__ __forceinline__ uint32_t smem_u32(const void* p) {
    uint32_t a;
    asm("{ .reg .u64 t; cvta.to.shared.u64 t, %1; cvt.u32.u64 %0, t; }" : "=r"(a) : "l"(p));
    return a;
}

#define SWZ(off) ((off) ^ (((off) >> 3) & 0x70))

__device__ __forceinline__ void ldmx4(uint32_t* r, uint32_t addr) {
    asm volatile("ldmatrix.sync.aligned.m8n8.x4.shared.b16 {%0,%1,%2,%3}, [%4];"
                 : "=r"(r[0]), "=r"(r[1]), "=r"(r[2]), "=r"(r[3]) : "r"(addr));
}

__device__ __forceinline__ void mma_bf16(float* d, const uint32_t* a, const uint32_t* b) {
    asm volatile(
        "mma.sync.aligned.m16n8k16.row.col.f32.bf16.bf16.f32 "
        "{%0,%1,%2,%3}, {%4,%5,%6,%7}, {%8,%9}, {%0,%1,%2,%3};"
        : "+f"(d[0]), "+f"(d[1]), "+f"(d[2]), "+f"(d[3])
        : "r"(a[0]), "r"(a[1]), "r"(a[2]), "r"(a[3]), "r"(b[0]), "r"(b[1]));
}

__device__ __forceinline__ void cpa16(uint32_t saddr, const void* g, bool pred) {
    asm volatile("cp.async.cg.shared.global [%0], [%1], 16, %2;"
                 :: "r"(saddr), "l"(g), "r"(pred ? 16 : 0) : "memory");
}
#define CP_COMMIT() asm volatile("cp.async.commit_group;" ::: "memory")
#define CP_WAIT(n)  asm volatile("cp.async.wait_group %0;" :: "n"(n) : "memory")

__device__ __forceinline__ uint32_t pack_hi2(float a, float b) {
    __nv_bfloat16 ha = __float2bfloat16(a), hb = __float2bfloat16(b);
    return (uint32_t)__bfloat16_as_ushort(ha) | ((uint32_t)__bfloat16_as_ushort(hb) << 16);
}
__device__ __forceinline__ uint32_t pack_lo2(float a, float b) {
    __nv_bfloat16 ha = __float2bfloat16(a), hb = __float2bfloat16(b);
    __nv_bfloat16 la = __float2bfloat16(a - __bfloat162float(ha));
    __nv_bfloat16 lb = __float2bfloat16(b - __bfloat162float(hb));
    return (uint32_t)__bfloat16_as_ushort(la) | ((uint32_t)__bfloat16_as_ushort(lb) << 16);
}
// biased int16 pack: q' = round(v*sinv) + 32768
__device__ __forceinline__ uint32_t packs16b(float a, float b, float sinv) {
    int qa = __float2int_rn(a * sinv) + 32768;
    int qb = __float2int_rn(b * sinv) + 32768;
    return ((uint32_t)qa & 0xffffu) | ((uint32_t)qb << 16);
}
// biased extraction (non-critical paths)
__device__ __forceinline__ float ub_lo(uint32_t u) { return (float)(int)(u & 0xffffu) - 32768.f; }
__device__ __forceinline__ float ub_hi(uint32_t u) { return (float)(u >> 16) - 32768.f; }
// magic constant for PRMT dequant: 2^23 + 32768
#define MAGIC_C 8421376.f

// ======================= graph preprocessing =======================
__global__ void k_zero_deg() {
    int i = blockIdx.x * blockDim.x + threadIdx.x;
    if (i < NN) g_deg[i] = 0;
}
__global__ void k_hist(const int* __restrict__ dst) {
    int e = blockIdx.x * blockDim.x + threadIdx.x;
    if (e < NE) atomicAdd(&g_deg[dst[e]], 1);
}
__global__ void k_dinv() {
    int i = blockIdx.x * blockDim.x + threadIdx.x;
    if (i < NN) {
        int d = g_deg[i];
        float df = (float)(d > 1 ? d : 1);
        g_dinv[i] = rsqrtf(df);
        g_rdinv[i] = sqrtf(df);
    }
}

__global__ void __launch_bounds__(1024) k_scanA() {
    __shared__ int wsum[32];
    int t = threadIdx.x, lane = t & 31, wp = t >> 5;
    int i = blockIdx.x * 1024 + t;
    int v = (i < NN) ? g_deg[i] : 0;
    int x = v;
    #pragma unroll
    for (int o = 1; o < 32; o <<= 1) {
        int y = __shfl_up_sync(0xffffffffu, x, o);
        if (lane >= o) x += y;
    }
    if (lane == 31) wsum[wp] = x;
    __syncthreads();
    if (wp == 0) {
        int s = wsum[lane];
        #pragma unroll
        for (int o = 1; o < 32; o <<= 1) {
            int y = __shfl_up_sync(0xffffffffu, s, o);
            if (lane >= o) s += y;
        }
        wsum[lane] = s;
    }
    __syncthreads();
    int off = (wp ? wsum[wp - 1] : 0);
    if (i < NN) g_rowoff[i] = off + x - v;
    if (t == 1023) g_bsum[blockIdx.x] = wsum[31];
}

__global__ void k_scanB(int nb) {
    __shared__ int sh[4];
    int t = threadIdx.x, lane = t & 31, wp = t >> 5;
    int v = (t < nb) ? g_bsum[t] : 0;
    int x = v;
    #pragma unroll
    for (int o = 1; o < 32; o <<= 1) {
        int y = __shfl_up_sync(0xffffffffu, x, o);
        if (lane >= o) x += y;
    }
    if (lane == 31) sh[wp] = x;
    __syncthreads();
    int add = 0;
    for (int w = 0; w < wp; ++w) add += sh[w];
    if (t < 128) g_boff[t] = add + x - v;
}

__global__ void k_scanC() {
    int i = blockIdx.x * blockDim.x + threadIdx.x;
    if (i < NN) {
        int r = g_rowoff[i] + g_boff[i >> 10];
        g_rowoff[i] = r;
        g_cursor[i] = r;
    }
    if (i == 0) g_rowoff[NN] = NE;
}

__global__ void k_scatter(const int* __restrict__ src, const int* __restrict__ dst) {
    int e = blockIdx.x * blockDim.x + threadIdx.x;
    if (e < NE) {
        int p = atomicAdd(&g_cursor[dst[e]], 1);
        g_csr[p] = src[e];
    }
}

// ======================= input conversion (warp per row) =======================
__global__ void k_featsplit(const float* __restrict__ f) {
    int w = (blockIdx.x * blockDim.x + threadIdx.x) >> 5;
    int lane = threadIdx.x & 31;
    if (w >= NN) return;
    float dv = g_dinv[w];
    size_t base = (size_t)w * FH + lane * 4;
    float4 v = *(const float4*)(f + base);
    float p0 = v.x * dv, p1 = v.y * dv, p2 = v.z * dv, p3 = v.w * dv;
    float m = fmaxf(fmaxf(fabsf(p0), fabsf(p1)), fmaxf(fabsf(p2), fabsf(p3)));
    #pragma unroll
    for (int o = 16; o >= 1; o >>= 1) m = fmaxf(m, __shfl_xor_sync(0xffffffffu, m, o));
    float sinv = (m > 0.f) ? (32766.f / m) : 0.f;
    uint2 q;
    q.x = packs16b(p0, p1, sinv);
    q.y = packs16b(p2, p3, sinv);
    *(uint2*)(&g_I0[0][base]) = q;
    if (lane == 0) g_S0[0][w] = m * (1.f / 32766.f);
}

__global__ void k_prep_w(const float* __restrict__ W0, const float* __restrict__ Wh) {
    int i = blockIdx.x * blockDim.x + threadIdx.x;
    if (i >= 6 * 384 * 128) return;
    int l = i / (384 * 128);
    int r = i % (384 * 128);
    int k = r / 128, n = r % 128;
    const float* W = (l == 0) ? W0 : (Wh + (size_t)(l - 1) * 384 * 128);
    float v = W[(size_t)k * 128 + n];
    __nv_bfloat16 h = __float2bfloat16(v);
    float lo = v - __bfloat162float(h);
    size_t o = (size_t)l * 128 * 384 + (size_t)n * 384 + k;
    g_Wth[o] = h;
    g_Wtl[o] = __float2bfloat16(lo);
}

// ======================= SpMM v3: half-warp per edge, PRMT dequant ===============
// Each warp handles one node; lanes 0-15 process even edges, 16-31 odd edges.
// Each lane loads uint4 (8 biased int16 features). Dequant: PRMT-magic + exact FADD.
// MODE 1: X1p = -dv^2 * sum       MODE 2: X2p = -2*dv^2 * sum - X0p[w]
template <int MODE>
__global__ void __launch_bounds__(256) k_spmm(
    const unsigned short* __restrict__ Yq, const float* __restrict__ Ys,
    const unsigned short* __restrict__ X0q, const float* __restrict__ X0s,
    unsigned short* __restrict__ oq, float* __restrict__ os) {
    int w = (blockIdx.x * blockDim.x + threadIdx.x) >> 5;
    int lane = threadIdx.x & 31;
    if (w >= NN) return;
    int beg = g_rowoff[w];
    int end = g_rowoff[w + 1];
    const int half = lane >> 4, sub = lane & 15;

    float a0 = 0.f, a1 = 0.f, a2 = 0.f, a3 = 0.f;
    float a4 = 0.f, a5 = 0.f, a6 = 0.f, a7 = 0.f;

    for (int i = beg; i < end; i += 2) {
        int e = i + half;
        bool ok = e < end;
        int s = g_csr[ok ? e : i];
        float c = ok ? Ys[s] : 0.f;
        uint4 u = *(const uint4*)(Yq + (size_t)s * FH + sub * 8);
        float f;
        f = __uint_as_float(__byte_perm(u.x, 0x4B000000u, 0x7410)) - MAGIC_C; a0 = fmaf(f, c, a0);
        f = __uint_as_float(__byte_perm(u.x, 0x4B000000u, 0x7432)) - MAGIC_C; a1 = fmaf(f, c, a1);
        f = __uint_as_float(__byte_perm(u.y, 0x4B000000u, 0x7410)) - MAGIC_C; a2 = fmaf(f, c, a2);
        f = __uint_as_float(__byte_perm(u.y, 0x4B000000u, 0x7432)) - MAGIC_C; a3 = fmaf(f, c, a3);
        f = __uint_as_float(__byte_perm(u.z, 0x4B000000u, 0x7410)) - MAGIC_C; a4 = fmaf(f, c, a4);
        f = __uint_as_float(__byte_perm(u.z, 0x4B000000u, 0x7432)) - MAGIC_C; a5 = fmaf(f, c, a5);
        f = __uint_as_float(__byte_perm(u.w, 0x4B000000u, 0x7410)) - MAGIC_C; a6 = fmaf(f, c, a6);
        f = __uint_as_float(__byte_perm(u.w, 0x4B000000u, 0x7432)) - MAGIC_C; a7 = fmaf(f, c, a7);
    }
    // combine the two half-warps (lane i and i+16 hold the same 8 feature slots)
    a0 += __shfl_xor_sync(0xffffffffu, a0, 16);
    a1 += __shfl_xor_sync(0xffffffffu, a1, 16);
    a2 += __shfl_xor_sync(0xffffffffu, a2, 16);
    a3 += __shfl_xor_sync(0xffffffffu, a3, 16);
    a4 += __shfl_xor_sync(0xffffffffu, a4, 16);
    a5 += __shfl_xor_sync(0xffffffffu, a5, 16);
    a6 += __shfl_xor_sync(0xffffffffu, a6, 16);
    a7 += __shfl_xor_sync(0xffffffffu, a7, 16);

    float dv = g_dinv[w];
    float dv2 = dv * dv;
    float p0, p1, p2, p3, p4, p5, p6, p7;
    if (MODE == 1) {
        float m = -dv2;
        p0 = m * a0; p1 = m * a1; p2 = m * a2; p3 = m * a3;
        p4 = m * a4; p5 = m * a5; p6 = m * a6; p7 = m * a7;
    } else {
        float xs = X0s[w];
        uint4 xq = *(const uint4*)(X0q + (size_t)w * FH + sub * 8);
        float m = -2.f * dv2;
        p0 = fmaf(m, a0, -ub_lo(xq.x) * xs);
        p1 = fmaf(m, a1, -ub_hi(xq.x) * xs);
        p2 = fmaf(m, a2, -ub_lo(xq.y) * xs);
        p3 = fmaf(m, a3, -ub_hi(xq.y) * xs);
        p4 = fmaf(m, a4, -ub_lo(xq.z) * xs);
        p5 = fmaf(m, a5, -ub_hi(xq.z) * xs);
        p6 = fmaf(m, a6, -ub_lo(xq.w) * xs);
        p7 = fmaf(m, a7, -ub_hi(xq.w) * xs);
    }
    float mx = fmaxf(fmaxf(fmaxf(fabsf(p0), fabsf(p1)), fmaxf(fabsf(p2), fabsf(p3))),
                     fmaxf(fmaxf(fabsf(p4), fabsf(p5)), fmaxf(fabsf(p6), fabsf(p7))));
    #pragma unroll
    for (int o = 8; o >= 1; o >>= 1) mx = fmaxf(mx, __shfl_xor_sync(0xffffffffu, mx, o));
    // halves hold identical values; reduction over sub-lanes 0-15 suffices (dup in 16-31)
    float sinv = (mx > 0.f) ? (32766.f / mx) : 0.f;
    if (half == 0) {
        uint4 q;
        q.x = packs16b(p0, p1, sinv);
        q.y = packs16b(p2, p3, sinv);
        q.z = packs16b(p4, p5, sinv);
        q.w = packs16b(p6, p7, sinv);
        *(uint4*)(oq + (size_t)w * FH + sub * 8) = q;
    }
    if (lane == 0) os[w] = mx * (1.f / 32766.f);
}

// ======================= pipelined mma.sync GEMM, int16 A with smem dequant ======
// C = relu( rdinv[m] * ([X0p|X1p|X2p] @ W) + b ); p = C*dinv[m]; store biased int16+scale.
#define GS_SCR 0
#define GS_AHI 16384
#define GS_ALO 32768
#define GS_BHI 49152
#define GS_BLO 65536
#define GS_ST  81920
#define GM_SMEM_SZ (2 * GS_ST)

__global__ void __launch_bounds__(512) k_gemm_mma(
    const unsigned short* __restrict__ x0q, const float* __restrict__ x0s,
    const float* __restrict__ bias,
    const __nv_bfloat16* __restrict__ wth, const __nv_bfloat16* __restrict__ wtl,
    unsigned short* __restrict__ outq, float* __restrict__ outs) {
    extern __shared__ char smem_raw[];
    __shared__ float s_bias[128];
    __shared__ float s_scl[3][128];
    __shared__ float s_rmax[128][4];
    uint32_t sb0 = smem_u32(smem_raw);
    uint32_t sb = (sb0 + 1023u) & ~1023u;          // 1024B-align for SW128
    char* smc = smem_raw + (sb - sb0);

    const int tid = threadIdx.x, lane = tid & 31, wid = tid >> 5;
    const int wm = wid >> 2, wn = wid & 3;         // 4x4 warp grid
    const int rowBase = blockIdx.x * 128;

    const unsigned short* Aq[3] = {x0q, g_I1, g_I2};
    const float* Sq[3] = {x0s, g_S1, g_S2};
    if (tid < 128) {
        s_bias[tid] = bias[tid];
        int row = rowBase + tid;
        bool ok = row < NN;
        #pragma unroll
        for (int b = 0; b < 3; ++b)
            s_scl[b][tid] = ok ? Sq[b][row] : 0.f;
    }
    __syncthreads();

    float acc[2][4][4];
    #pragma unroll
    for (int a = 0; a < 2; ++a)
        #pragma unroll
        for (int b = 0; b < 4; ++b)
            #pragma unroll
            for (int c = 0; c < 4; ++c) acc[a][b][c] = 0.f;

    const int lrow = lane & 7, seg = lane >> 3;

    auto load_chunk = [&](uint32_t st, int kc) {
        const int coff = (kc & 1) * 64;
        const unsigned short* __restrict__ aq = Aq[kc >> 1];
        #pragma unroll
        for (int t = 0; t < 2; ++t) {
            int idx = tid + t * 512;
            int r = idx >> 3, j = idx & 7;
            int row = rowBase + r;
            bool ok = row < NN;
            int rowc = ok ? row : (NN - 1);
            cpa16(st + GS_SCR + (uint32_t)(r * 128 + j * 16),
                  aq + (size_t)rowc * FH + coff + j * 8, ok);
        }
        #pragma unroll
        for (int t = 0; t < 2; ++t) {
            int idx = tid + t * 512;
            int n = idx >> 3, j = idx & 7;
            uint32_t sw = SWZ((uint32_t)(n * 128 + j * 16));
            cpa16(st + GS_BHI + sw, wth + (size_t)n * 384 + kc * 64 + j * 8, true);
            cpa16(st + GS_BLO + sw, wtl + (size_t)n * 384 + kc * 64 + j * 8, true);
        }
    };

    load_chunk(sb, 0);
    CP_COMMIT();

    #pragma unroll 1
    for (int kc = 0; kc < 6; ++kc) {
        if (kc < 5) {
            load_chunk(sb + (((kc + 1) & 1) ? GS_ST : 0), kc + 1);
            CP_COMMIT();
            CP_WAIT(1);
        } else {
            CP_WAIT(0);
        }
        __syncthreads();

        const uint32_t st = sb + ((kc & 1) ? GS_ST : 0);
        char* stc = smc + ((kc & 1) ? GS_ST : 0);
        // dequant scratch biased-int16 -> A hi/lo bf16 planes
        {
            const float* sc = s_scl[kc >> 1];
            #pragma unroll
            for (int t = 0; t < 2; ++t) {
                int idx = tid + t * 512;
                int r = idx >> 3, j = idx & 7;
                uint4 u = *(const uint4*)(stc + GS_SCR + (uint32_t)(r * 128 + j * 16));
                float s = sc[r];
                float v0 = ub_lo(u.x) * s, v1 = ub_hi(u.x) * s;
                float v2 = ub_lo(u.y) * s, v3 = ub_hi(u.y) * s;
                float v4 = ub_lo(u.z) * s, v5 = ub_hi(u.z) * s;
                float v6 = ub_lo(u.w) * s, v7 = ub_hi(u.w) * s;
                uint4 h, l;
                h.x = pack_hi2(v0, v1); l.x = pack_lo2(v0, v1);
                h.y = pack_hi2(v2, v3); l.y = pack_lo2(v2, v3);
                h.z = pack_hi2(v4, v5); l.z = pack_lo2(v4, v5);
                h.w = pack_hi2(v6, v7); l.w = pack_lo2(v6, v7);
                uint32_t sw = SWZ((uint32_t)(r * 128 + j * 16));
                *(uint4*)(stc + GS_AHI + sw) = h;
                *(uint4*)(stc + GS_ALO + sw) = l;
            }
        }
        __syncthreads();

        #pragma unroll
        for (int kt = 0; kt < 4; ++kt) {
            uint32_t Ahf[2][4], Alf[2][4], Bhf[2][4], Blf[2][4];
            #pragma unroll
            for (int mt = 0; mt < 2; ++mt) {
                int m = wm * 32 + mt * 16 + (seg & 1) * 8 + lrow;
                int kb = kt * 32 + (seg >> 1) * 16;
                uint32_t sw = SWZ((uint32_t)(m * 128 + kb));
                ldmx4(Ahf[mt], st + GS_AHI + sw);
                ldmx4(Alf[mt], st + GS_ALO + sw);
            }
            #pragma unroll
            for (int ntp = 0; ntp < 2; ++ntp) {
                int n = wn * 32 + ntp * 16 + (seg >> 1) * 8 + lrow;
                int kb = kt * 32 + (seg & 1) * 16;
                uint32_t sw = SWZ((uint32_t)(n * 128 + kb));
                ldmx4(Bhf[ntp], st + GS_BHI + sw);
                ldmx4(Blf[ntp], st + GS_BLO + sw);
            }
            #pragma unroll
            for (int mt = 0; mt < 2; ++mt)
                #pragma unroll
                for (int ntp = 0; ntp < 2; ++ntp)
                    #pragma unroll
                    for (int sub = 0; sub < 2; ++sub) {
                        int nj = ntp * 2 + sub;
                        mma_bf16(acc[mt][nj], Ahf[mt], &Bhf[ntp][sub * 2]);
                        mma_bf16(acc[mt][nj], Ahf[mt], &Blf[ntp][sub * 2]);
                        mma_bf16(acc[mt][nj], Alf[mt], &Bhf[ntp][sub * 2]);
                    }
        }
        __syncthreads();
    }

    // ---- epilogue: p = relu(acc*rdinv + b)*dinv; rowmax-quantize to biased int16 ----
    float dvr[2][2], rdr[2][2];
    #pragma unroll
    for (int mt = 0; mt < 2; ++mt)
        #pragma unroll
        for (int rp = 0; rp < 2; ++rp) {
            int row = rowBase + wm * 32 + mt * 16 + (lane >> 2) + rp * 8;
            bool ok = row < NN;
            dvr[mt][rp] = ok ? g_dinv[row] : 0.f;
            rdr[mt][rp] = ok ? g_rdinv[row] : 0.f;
        }
    float pm[2][2] = {{0.f, 0.f}, {0.f, 0.f}};
    #pragma unroll
    for (int mt = 0; mt < 2; ++mt)
        #pragma unroll
        for (int nj = 0; nj < 4; ++nj) {
            int col = wn * 32 + nj * 8 + (lane & 3) * 2;
            float bz0 = s_bias[col], bz1 = s_bias[col + 1];
            #pragma unroll
            for (int rp = 0; rp < 2; ++rp) {
                float rd = rdr[mt][rp], dv = dvr[mt][rp];
                float p0 = fmaxf(fmaf(acc[mt][nj][rp * 2 + 0], rd, bz0), 0.f) * dv;
                float p1 = fmaxf(fmaf(acc[mt][nj][rp * 2 + 1], rd, bz1), 0.f) * dv;
                pm[mt][rp] = fmaxf(pm[mt][rp], fmaxf(p0, p1));
            }
        }
    #pragma unroll
    for (int mt = 0; mt < 2; ++mt)
        #pragma unroll
        for (int rp = 0; rp < 2; ++rp) {
            float m = pm[mt][rp];
            m = fmaxf(m, __shfl_xor_sync(0xffffffffu, m, 1));
            m = fmaxf(m, __shfl_xor_sync(0xffffffffu, m, 2));
            if ((lane & 3) == 0)
                s_rmax[wm * 32 + mt * 16 + rp * 8 + (lane >> 2)][wn] = m;
        }
    __syncthreads();
    #pragma unroll
    for (int mt = 0; mt < 2; ++mt)
        #pragma unroll
        for (int rp = 0; rp < 2; ++rp) {
            int rl = wm * 32 + mt * 16 + rp * 8 + (lane >> 2);
            int row = rowBase + rl;
            float rm = fmaxf(fmaxf(s_rmax[rl][0], s_rmax[rl][1]),
                             fmaxf(s_rmax[rl][2], s_rmax[rl][3]));
            float sinv = (rm > 0.f) ? (32766.f / rm) : 0.f;
            if (wn == 0 && (lane & 3) == 0 && row < NN)
                outs[row] = rm * (1.f / 32766.f);
            if (row < NN) {
                float rd = rdr[mt][rp], dv = dvr[mt][rp];
                #pragma unroll
                for (int nj = 0; nj < 4; ++nj) {
                    int col = wn * 32 + nj * 8 + (lane & 3) * 2;
                    float bz0 = s_bias[col], bz1 = s_bias[col + 1];
                    float p0 = fmaxf(fmaf(acc[mt][nj][rp * 2 + 0], rd, bz0), 0.f) * dv;
                    float p1 = fmaxf(fmaf(acc[mt][nj][rp * 2 + 1], rd, bz1), 0.f) * dv;
                    *(uint32_t*)(outq + (size_t)row * FH + col) = packs16b(p0, p1, sinv);
                }
            }
        }
}

// ======================= SIMT GEMM for final layer (CO=40) =======================
template <int CO, int TM, int TN>
__global__ void k_gemm_simt(
    const unsigned short* __restrict__ X0q, const float* __restrict__ X0s,
    const unsigned short* __restrict__ X1q, const float* __restrict__ X1s,
    const unsigned short* __restrict__ X2q, const float* __restrict__ X2s,
    const float* __restrict__ W, const float* __restrict__ bias,
    float* __restrict__ out) {
    constexpr int BM = 128, BK = 16;
    constexpr int NTX = CO / TN;
    constexpr int NTY = BM / TM;
    constexpr int NT = NTX * NTY;
    __shared__ float As[BK][BM + 1];
    __shared__ float Bs[BK][CO];
    const int tid = threadIdx.x;
    const int tx = tid % NTX;
    const int ty = tid / NTX;
    const int rowBase = blockIdx.x * BM;

    float acc[TM][TN];
    #pragma unroll
    for (int m = 0; m < TM; ++m)
        #pragma unroll
        for (int n = 0; n < TN; ++n) acc[m][n] = 0.f;

    #pragma unroll 1
    for (int kt = 0; kt < 24; ++kt) {
        const unsigned short* __restrict__ Xq = (kt < 8) ? X0q : ((kt < 16) ? X1q : X2q);
        const float* __restrict__ Xs = (kt < 8) ? X0s : ((kt < 16) ? X1s : X2s);
        const int kcol = (kt & 7) * BK;
        for (int i = tid; i < BM * BK; i += NT) {
            int r = i >> 4, k = i & 15;
            int row = rowBase + r;
            float v = 0.f;
            if (row < NN) {
                size_t off = (size_t)row * FH + kcol + k;
                v = ((float)(int)Xq[off] - 32768.f) * Xs[row] * g_rdinv[row];
            }
            As[k][r] = v;
        }
        for (int i = tid; i < BK * CO; i += NT) {
            int k = i / CO, c = i % CO;
            Bs[k][c] = W[(size_t)(kt * BK + k) * CO + c];
        }
        __syncthreads();
        #pragma unroll
        for (int k = 0; k < BK; ++k) {
            float ra[TM], rb[TN];
            #pragma unroll
            for (int m = 0; m < TM; ++m) ra[m] = As[k][ty * TM + m];
            #pragma unroll
            for (int n = 0; n < TN; ++n) rb[n] = Bs[k][tx * TN + n];
            #pragma unroll
            for (int m = 0; m < TM; ++m)
                #pragma unroll
                for (int n = 0; n < TN; ++n)
                    acc[m][n] = fmaf(ra[m], rb[n], acc[m][n]);
        }
        __syncthreads();
    }
    #pragma unroll
    for (int m = 0; m < TM; ++m) {
        int row = rowBase + ty * TM + m;
        if (row < NN) {
            #pragma unroll
            for (int n = 0; n < TN; ++n) {
                int c = tx * TN + n;
                out[(size_t)row * CO + c] = fmaxf(acc[m][n] + bias[c], 0.f);
            }
        }
    }
}

// ======================= host launcher =======================
extern "C" void kernel_launch(void* const* d_in, const int* in_sizes, int n_in,
                              void* d_out, int out_size) {
    const float* feat = (const float*)d_in[0];
    const int*   src  = (const int*)d_in[1];
    const int*   dst  = (const int*)d_in[2];
    const float* W0   = (const float*)d_in[3];
    const float* b0   = (const float*)d_in[4];
    const float* Wh   = (const float*)d_in[5];
    const float* bh   = (const float*)d_in[6];
    const float* Wl   = (const float*)d_in[7];
    const float* bl   = (const float*)d_in[8];
    float* out = (float*)d_out;

    unsigned short *I0, *I1, *I2;
    float *S0, *S1, *S2;
    __nv_bfloat16 *Wth, *Wtl;
    cudaGetSymbolAddress((void**)&I0,  g_I0);
    cudaGetSymbolAddress((void**)&I1,  g_I1);
    cudaGetSymbolAddress((void**)&I2,  g_I2);
    cudaGetSymbolAddress((void**)&S0,  g_S0);
    cudaGetSymbolAddress((void**)&S1,  g_S1);
    cudaGetSymbolAddress((void**)&S2,  g_S2);
    cudaGetSymbolAddress((void**)&Wth, g_Wth);
    cudaGetSymbolAddress((void**)&Wtl, g_Wtl);

    cudaFuncSetAttribute(k_gemm_mma, cudaFuncAttributeMaxDynamicSharedMemorySize,
                         GM_SMEM_SZ + 1024);

    const int TPB = 256;
    const int nodeBlocks = (NN + TPB - 1) / TPB;
    const int edgeBlocks = (NE + TPB - 1) / TPB;
    const int scanBlocks = (NN + 1023) / 1024;   // 98

    // preprocessing
    k_zero_deg<<<nodeBlocks, TPB>>>();
    k_hist<<<edgeBlocks, TPB>>>(dst);
    k_dinv<<<nodeBlocks, TPB>>>();
    k_scanA<<<scanBlocks, 1024>>>();
    k_scanB<<<1, 128>>>(scanBlocks);
    k_scanC<<<nodeBlocks, TPB>>>();
    k_scatter<<<edgeBlocks, TPB>>>(src, dst);

    // input conversion (warp per row)
    k_featsplit<<<(NN * 32 + TPB - 1) / TPB, TPB>>>(feat);
    k_prep_w<<<(6 * 384 * 128 + TPB - 1) / TPB, TPB>>>(W0, Wh);

    const size_t SL = (size_t)NN * FH;
    const int spmmBlocks = (NN * 32 + TPB - 1) / TPB;
    const int tileBlocks = (NN + 127) / 128;

    int cur = 0;
    for (int l = 0; l < 7; ++l) {
        const unsigned short* I0c = I0 + (size_t)cur * SL;
        const float* S0c = S0 + (size_t)cur * NN;
        k_spmm<1><<<spmmBlocks, TPB>>>(I0c, S0c, nullptr, nullptr, I1, S1);
        k_spmm<2><<<spmmBlocks, TPB>>>(I1, S1, I0c, S0c, I2, S2);
        if (l < 6) {
            const float* bias = (l == 0) ? b0 : (bh + (size_t)(l - 1) * 128);
            int nxt = 1 - cur;
            k_gemm_mma<<<tileBlocks, 512, GM_SMEM_SZ + 1024>>>(
                I0c, S0c, bias,
                Wth + (size_t)l * 128 * 384, Wtl + (size_t)l * 128 * 384,
                I0 + (size_t)nxt * SL, S0 + (size_t)nxt * NN);
            cur = nxt;
        } else {
            k_gemm_simt<FO, 8, 5><<<tileBlocks, 128>>>(
                I0c, S0c, I1, S1, I2, S2, Wl, bl, out);
        }
    }
}

// round 9
// speedup vs baseline: 1.0427x; 1.0427x over previous
#include <cuda_runtime.h>
#include <cuda_bf16.h>
#include <cstdint>

#define NN 100000
#define NE 1600000
#define FH 128
#define FO 40

// ======================= device scratch (no allocs allowed) =======================
__device__ int   g_deg[NN];
__device__ float g_dinv[NN];
__device__ float g_rdinv[NN];
__device__ int   g_rowoff[NN + 1];
__device__ int   g_cursor[NN];
__device__ int   g_csr[NE];
__device__ int   g_bsum[128];
__device__ int   g_boff[128];

// int16 row-quantized prescaled activation planes (x*dinv ~= s_row * q)
__device__ unsigned short g_I0[2][(size_t)NN * FH];
__device__ float g_S0[2][NN];
__device__ unsigned short g_I1[(size_t)NN * FH];
__device__ float g_S1[NN];
__device__ unsigned short g_I2[(size_t)NN * FH];
__device__ float g_S2[NN];
// weights (exact hi/lo bf16 split)
__device__ __nv_bfloat16 g_Wth[6 * 128 * 384];   // W^T per layer: [n=128][k=384], hi
__device__ __nv_bfloat16 g_Wtl[6 * 128 * 384];   // lo

// ======================= helpers =======================
__device__ __forceinline__ uint32_t smem_u32(const void* p) {
    uint32_t a;
    asm("{ .reg .u64 t; cvta.to.shared.u64 t, %1; cvt.u32.u64 %0, t; }" : "=r"(a) : "l"(p));
    return a;
}

#define SWZ(off) ((off) ^ (((off) >> 3) & 0x70))

__device__ __forceinline__ void ldmx4(uint32_t* r, uint32_t addr) {
    asm volatile("ldmatrix.sync.aligned.m8n8.x4.shared.b16 {%0,%1,%2,%3}, [%4];"
                 : "=r"(r[0]), "=r"(r[1]), "=r"(r[2]), "=r"(r[3]) : "r"(addr));
}

__device__ __forceinline__ void mma_bf16(float* d, const uint32_t* a, const uint32_t* b) {
    asm volatile(
        "mma.sync.aligned.m16n8k16.row.col.f32.bf16.bf16.f32 "
        "{%0,%1,%2,%3}, {%4,%5,%6,%7}, {%8,%9}, {%0,%1,%2,%3};"
        : "+f"(d[0]), "+f"(d[1]), "+f"(d[2]), "+f"(d[3])
        : "r"(a[0]), "r"(a[1]), "r"(a[2]), "r"(a[3]), "r"(b[0]), "r"(b[1]));
}

__device__ __forceinline__ void cpa16(uint32_t saddr, const void* g, bool pred) {
    asm volatile("cp.async.cg.shared.global [%0], [%1], 16, %2;"
                 :: "r"(saddr), "l"(g), "r"(pred ? 16 : 0) : "memory");
}
#define CP_COMMIT() asm volatile("cp.async.commit_group;" ::: "memory")
#define CP_WAIT(n)  asm volatile("cp.async.wait_group %0;" :: "n"(n) : "memory")

__device__ __forceinline__ uint32_t pack_hi2(float a, float b) {
    __nv_bfloat16 ha = __float2bfloat16(a), hb = __float2bfloat16(b);
    return (uint32_t)__bfloat16_as_ushort(ha) | ((uint32_t)__bfloat16_as_ushort(hb) << 16);
}
__device__ __forceinline__ uint32_t pack_lo2(float a, float b) {
    __nv_bfloat16 ha = __float2bfloat16(a), hb = __float2bfloat16(b);
    __nv_bfloat16 la = __float2bfloat16(a - __bfloat162float(ha));
    __nv_bfloat16 lb = __float2bfloat16(b - __bfloat162float(hb));
    return (uint32_t)__bfloat16_as_ushort(la) | ((uint32_t)__bfloat16_as_ushort(lb) << 16);
}
__device__ __forceinline__ uint32_t packs16(float a, float b, float sinv) {
    int qa = __float2int_rn(a * sinv);
    int qb = __float2int_rn(b * sinv);
    return ((uint32_t)qa & 0xffffu) | ((uint32_t)qb << 16);
}
__device__ __forceinline__ float slo(uint32_t u) { return (float)(short)(u & 0xffffu); }
__device__ __forceinline__ float shi(uint32_t u) { return (float)((int)u >> 16); }

// ======================= graph preprocessing =======================
__global__ void k_hist(const int* __restrict__ dst) {
    int e = blockIdx.x * blockDim.x + threadIdx.x;
    if (e < NE) atomicAdd(&g_deg[dst[e]], 1);
}

__global__ void __launch_bounds__(1024) k_scanA() {
    __shared__ int wsum[32];
    int t = threadIdx.x, lane = t & 31, wp = t >> 5;
    int i = blockIdx.x * 1024 + t;
    int v = (i < NN) ? g_deg[i] : 0;
    int x = v;
    #pragma unroll
    for (int o = 1; o < 32; o <<= 1) {
        int y = __shfl_up_sync(0xffffffffu, x, o);
        if (lane >= o) x += y;
    }
    if (lane == 31) wsum[wp] = x;
    __syncthreads();
    if (wp == 0) {
        int s = wsum[lane];
        #pragma unroll
        for (int o = 1; o < 32; o <<= 1) {
            int y = __shfl_up_sync(0xffffffffu, s, o);
            if (lane >= o) s += y;
        }
        wsum[lane] = s;
    }
    __syncthreads();
    int off = (wp ? wsum[wp - 1] : 0);
    if (i < NN) g_rowoff[i] = off + x - v;
    if (t == 1023) g_bsum[blockIdx.x] = wsum[31];
}

__global__ void k_scanB(int nb) {
    __shared__ int sh[4];
    int t = threadIdx.x, lane = t & 31, wp = t >> 5;
    int v = (t < nb) ? g_bsum[t] : 0;
    int x = v;
    #pragma unroll
    for (int o = 1; o < 32; o <<= 1) {
        int y = __shfl_up_sync(0xffffffffu, x, o);
        if (lane >= o) x += y;
    }
    if (lane == 31) sh[wp] = x;
    __syncthreads();
    int add = 0;
    for (int w = 0; w < wp; ++w) add += sh[w];
    if (t < 128) g_boff[t] = add + x - v;
}

// scanC + dinv fused
__global__ void k_scanC() {
    int i = blockIdx.x * blockDim.x + threadIdx.x;
    if (i < NN) {
        int r = g_rowoff[i] + g_boff[i >> 10];
        g_rowoff[i] = r;
        g_cursor[i] = r;
        int d = g_deg[i];
        float df = (float)(d > 1 ? d : 1);
        g_dinv[i] = rsqrtf(df);
        g_rdinv[i] = sqrtf(df);
    }
    if (i == 0) g_rowoff[NN] = NE;
}

__global__ void k_scatter(const int* __restrict__ src, const int* __restrict__ dst) {
    int e = blockIdx.x * blockDim.x + threadIdx.x;
    if (e < NE) {
        int p = atomicAdd(&g_cursor[dst[e]], 1);
        g_csr[p] = src[e];
    }
}

// ======================= input conversion (warp per row) =======================
__global__ void k_featsplit(const float* __restrict__ f) {
    int w = (blockIdx.x * blockDim.x + threadIdx.x) >> 5;
    int lane = threadIdx.x & 31;
    if (w >= NN) return;
    float dv = g_dinv[w];
    size_t base = (size_t)w * FH + lane * 4;
    float4 v = *(const float4*)(f + base);
    float p0 = v.x * dv, p1 = v.y * dv, p2 = v.z * dv, p3 = v.w * dv;
    float m = fmaxf(fmaxf(fabsf(p0), fabsf(p1)), fmaxf(fabsf(p2), fabsf(p3)));
    #pragma unroll
    for (int o = 16; o >= 1; o >>= 1) m = fmaxf(m, __shfl_xor_sync(0xffffffffu, m, o));
    float sinv = (m > 0.f) ? (32766.f / m) : 0.f;
    uint2 q;
    q.x = packs16(p0, p1, sinv);
    q.y = packs16(p2, p3, sinv);
    *(uint2*)(&g_I0[0][base]) = q;
    if (lane == 0) g_S0[0][w] = m * (1.f / 32766.f);
}

__global__ void k_prep_w(const float* __restrict__ W0, const float* __restrict__ Wh) {
    int i = blockIdx.x * blockDim.x + threadIdx.x;
    if (i >= 6 * 384 * 128) return;
    int l = i / (384 * 128);
    int r = i % (384 * 128);
    int k = r / 128, n = r % 128;
    const float* W = (l == 0) ? W0 : (Wh + (size_t)(l - 1) * 384 * 128);
    float v = W[(size_t)k * 128 + n];
    __nv_bfloat16 h = __float2bfloat16(v);
    float lo = v - __bfloat162float(h);
    size_t o = (size_t)l * 128 * 384 + (size_t)n * 384 + k;
    g_Wth[o] = h;
    g_Wtl[o] = __float2bfloat16(lo);
}

// ======================= SpMM: warp-per-node CSR gather, int16 in/out ============
// All planes prescaled by dinv. value = Ys[s] * q.
// MODE 1: X1p = -dv^2 * sum       MODE 2: X2p = -2*dv^2 * sum - X0p[w]
// CSR indices batched: one uint4 broadcast LDG per 4 edges (aligned, with peel).
template <int MODE>
__global__ void __launch_bounds__(256) k_spmm(
    const unsigned short* __restrict__ Yq, const float* __restrict__ Ys,
    const unsigned short* __restrict__ X0q, const float* __restrict__ X0s,
    unsigned short* __restrict__ oq, float* __restrict__ os) {
    int w = (blockIdx.x * blockDim.x + threadIdx.x) >> 5;
    int lane = threadIdx.x & 31;
    if (w >= NN) return;
    int beg = g_rowoff[w];
    int end = g_rowoff[w + 1];
    const size_t lo4 = (size_t)(lane * 4);
    float a0 = 0.f, a1 = 0.f, a2 = 0.f, a3 = 0.f;
    int i = beg;
    // peel to 16B-aligned csr index
    int aend = (beg + 3) & ~3;
    if (aend > end) aend = end;
    for (; i < aend; ++i) {
        int s0 = g_csr[i];
        float c0 = Ys[s0];
        uint2 u0 = *(const uint2*)(Yq + (size_t)s0 * FH + lo4);
        a0 = fmaf(slo(u0.x), c0, a0); a1 = fmaf(shi(u0.x), c0, a1);
        a2 = fmaf(slo(u0.y), c0, a2); a3 = fmaf(shi(u0.y), c0, a3);
    }
    for (; i + 4 <= end; i += 4) {
        uint4 e = *(const uint4*)(g_csr + i);   // one broadcast LDG.128 for 4 edges
        int s0 = (int)e.x, s1 = (int)e.y, s2 = (int)e.z, s3 = (int)e.w;
        float c0 = Ys[s0], c1 = Ys[s1], c2 = Ys[s2], c3 = Ys[s3];
        uint2 u0 = *(const uint2*)(Yq + (size_t)s0 * FH + lo4);
        uint2 u1 = *(const uint2*)(Yq + (size_t)s1 * FH + lo4);
        uint2 u2 = *(const uint2*)(Yq + (size_t)s2 * FH + lo4);
        uint2 u3 = *(const uint2*)(Yq + (size_t)s3 * FH + lo4);
        a0 = fmaf(slo(u0.x), c0, a0); a1 = fmaf(shi(u0.x), c0, a1);
        a2 = fmaf(slo(u0.y), c0, a2); a3 = fmaf(shi(u0.y), c0, a3);
        a0 = fmaf(slo(u1.x), c1, a0); a1 = fmaf(shi(u1.x), c1, a1);
        a2 = fmaf(slo(u1.y), c1, a2); a3 = fmaf(shi(u1.y), c1, a3);
        a0 = fmaf(slo(u2.x), c2, a0); a1 = fmaf(shi(u2.x), c2, a1);
        a2 = fmaf(slo(u2.y), c2, a2); a3 = fmaf(shi(u2.y), c2, a3);
        a0 = fmaf(slo(u3.x), c3, a0); a1 = fmaf(shi(u3.x), c3, a1);
        a2 = fmaf(slo(u3.y), c3, a2); a3 = fmaf(shi(u3.y), c3, a3);
    }
    for (; i < end; ++i) {
        int s0 = g_csr[i];
        float c0 = Ys[s0];
        uint2 u0 = *(const uint2*)(Yq + (size_t)s0 * FH + lo4);
        a0 = fmaf(slo(u0.x), c0, a0); a1 = fmaf(shi(u0.x), c0, a1);
        a2 = fmaf(slo(u0.y), c0, a2); a3 = fmaf(shi(u0.y), c0, a3);
    }
    float dv = g_dinv[w];
    float dv2 = dv * dv;
    float p0, p1, p2, p3;
    if (MODE == 1) {
        float m = -dv2;
        p0 = m * a0; p1 = m * a1; p2 = m * a2; p3 = m * a3;
    } else {
        float xs = X0s[w];
        uint2 xq = *(const uint2*)(X0q + (size_t)w * FH + lo4);
        float m = -2.f * dv2;
        p0 = fmaf(m, a0, -slo(xq.x) * xs);
        p1 = fmaf(m, a1, -shi(xq.x) * xs);
        p2 = fmaf(m, a2, -slo(xq.y) * xs);
        p3 = fmaf(m, a3, -shi(xq.y) * xs);
    }
    float mx = fmaxf(fmaxf(fabsf(p0), fabsf(p1)), fmaxf(fabsf(p2), fabsf(p3)));
    #pragma unroll
    for (int o = 16; o >= 1; o >>= 1) mx = fmaxf(mx, __shfl_xor_sync(0xffffffffu, mx, o));
    float sinv = (mx > 0.f) ? (32766.f / mx) : 0.f;
    uint2 q;
    q.x = packs16(p0, p1, sinv);
    q.y = packs16(p2, p3, sinv);
    *(uint2*)(oq + (size_t)w * FH + lo4) = q;
    if (lane == 0) os[w] = mx * (1.f / 32766.f);
}

// ======================= pipelined mma.sync GEMM, int16 A with smem dequant ======
// C = relu( rdinv[m] * ([X0p|X1p|X2p] @ W) + b ); p = C*dinv[m]; store int16+scale.
#define GS_SCR 0
#define GS_AHI 16384
#define GS_ALO 32768
#define GS_BHI 49152
#define GS_BLO 65536
#define GS_ST  81920
#define GM_SMEM_SZ (2 * GS_ST)

__global__ void __launch_bounds__(512) k_gemm_mma(
    const unsigned short* __restrict__ x0q, const float* __restrict__ x0s,
    const float* __restrict__ bias,
    const __nv_bfloat16* __restrict__ wth, const __nv_bfloat16* __restrict__ wtl,
    unsigned short* __restrict__ outq, float* __restrict__ outs) {
    extern __shared__ char smem_raw[];
    __shared__ float s_bias[128];
    __shared__ float s_scl[3][128];
    __shared__ float s_rmax[128][4];
    uint32_t sb0 = smem_u32(smem_raw);
    uint32_t sb = (sb0 + 1023u) & ~1023u;          // 1024B-align for SW128
    char* smc = smem_raw + (sb - sb0);

    const int tid = threadIdx.x, lane = tid & 31, wid = tid >> 5;
    const int wm = wid >> 2, wn = wid & 3;         // 4x4 warp grid
    const int rowBase = blockIdx.x * 128;

    const unsigned short* Aq[3] = {x0q, g_I1, g_I2};
    const float* Sq[3] = {x0s, g_S1, g_S2};
    if (tid < 128) {
        s_bias[tid] = bias[tid];
        int row = rowBase + tid;
        bool ok = row < NN;
        #pragma unroll
        for (int b = 0; b < 3; ++b)
            s_scl[b][tid] = ok ? Sq[b][row] : 0.f;
    }
    __syncthreads();

    float acc[2][4][4];
    #pragma unroll
    for (int a = 0; a < 2; ++a)
        #pragma unroll
        for (int b = 0; b < 4; ++b)
            #pragma unroll
            for (int c = 0; c < 4; ++c) acc[a][b][c] = 0.f;

    const int lrow = lane & 7, seg = lane >> 3;

    auto load_chunk = [&](uint32_t st, int kc) {
        const int coff = (kc & 1) * 64;
        const unsigned short* __restrict__ aq = Aq[kc >> 1];
        #pragma unroll
        for (int t = 0; t < 2; ++t) {
            int idx = tid + t * 512;
            int r = idx >> 3, j = idx & 7;
            int row = rowBase + r;
            bool ok = row < NN;
            int rowc = ok ? row : (NN - 1);
            cpa16(st + GS_SCR + (uint32_t)(r * 128 + j * 16),
                  aq + (size_t)rowc * FH + coff + j * 8, ok);
        }
        #pragma unroll
        for (int t = 0; t < 2; ++t) {
            int idx = tid + t * 512;
            int n = idx >> 3, j = idx & 7;
            uint32_t sw = SWZ((uint32_t)(n * 128 + j * 16));
            cpa16(st + GS_BHI + sw, wth + (size_t)n * 384 + kc * 64 + j * 8, true);
            cpa16(st + GS_BLO + sw, wtl + (size_t)n * 384 + kc * 64 + j * 8, true);
        }
    };

    load_chunk(sb, 0);
    CP_COMMIT();

    #pragma unroll 1
    for (int kc = 0; kc < 6; ++kc) {
        if (kc < 5) {
            load_chunk(sb + (((kc + 1) & 1) ? GS_ST : 0), kc + 1);
            CP_COMMIT();
            CP_WAIT(1);
        } else {
            CP_WAIT(0);
        }
        __syncthreads();

        const uint32_t st = sb + ((kc & 1) ? GS_ST : 0);
        char* stc = smc + ((kc & 1) ? GS_ST : 0);
        // dequant scratch int16 -> A hi/lo bf16 planes
        {
            const float* sc = s_scl[kc >> 1];
            #pragma unroll
            for (int t = 0; t < 2; ++t) {
                int idx = tid + t * 512;
                int r = idx >> 3, j = idx & 7;
                uint4 u = *(const uint4*)(stc + GS_SCR + (uint32_t)(r * 128 + j * 16));
                float s = sc[r];
                float v0 = slo(u.x) * s, v1 = shi(u.x) * s;
                float v2 = slo(u.y) * s, v3 = shi(u.y) * s;
                float v4 = slo(u.z) * s, v5 = shi(u.z) * s;
                float v6 = slo(u.w) * s, v7 = shi(u.w) * s;
                uint4 h, l;
                h.x = pack_hi2(v0, v1); l.x = pack_lo2(v0, v1);
                h.y = pack_hi2(v2, v3); l.y = pack_lo2(v2, v3);
                h.z = pack_hi2(v4, v5); l.z = pack_lo2(v4, v5);
                h.w = pack_hi2(v6, v7); l.w = pack_lo2(v6, v7);
                uint32_t sw = SWZ((uint32_t)(r * 128 + j * 16));
                *(uint4*)(stc + GS_AHI + sw) = h;
                *(uint4*)(stc + GS_ALO + sw) = l;
            }
        }
        __syncthreads();

        #pragma unroll
        for (int kt = 0; kt < 4; ++kt) {
            uint32_t Ahf[2][4], Alf[2][4], Bhf[2][4], Blf[2][4];
            #pragma unroll
            for (int mt = 0; mt < 2; ++mt) {
                int m = wm * 32 + mt * 16 + (seg & 1) * 8 + lrow;
                int kb = kt * 32 + (seg >> 1) * 16;
                uint32_t sw = SWZ((uint32_t)(m * 128 + kb));
                ldmx4(Ahf[mt], st + GS_AHI + sw);
                ldmx4(Alf[mt], st + GS_ALO + sw);
            }
            #pragma unroll
            for (int ntp = 0; ntp < 2; ++ntp) {
                int n = wn * 32 + ntp * 16 + (seg >> 1) * 8 + lrow;
                int kb = kt * 32 + (seg & 1) * 16;
                uint32_t sw = SWZ((uint32_t)(n * 128 + kb));
                ldmx4(Bhf[ntp], st + GS_BHI + sw);
                ldmx4(Blf[ntp], st + GS_BLO + sw);
            }
            #pragma unroll
            for (int mt = 0; mt < 2; ++mt)
                #pragma unroll
                for (int ntp = 0; ntp < 2; ++ntp)
                    #pragma unroll
                    for (int sub = 0; sub < 2; ++sub) {
                        int nj = ntp * 2 + sub;
                        mma_bf16(acc[mt][nj], Ahf[mt], &Bhf[ntp][sub * 2]);
                        mma_bf16(acc[mt][nj], Ahf[mt], &Blf[ntp][sub * 2]);
                        mma_bf16(acc[mt][nj], Alf[mt], &Bhf[ntp][sub * 2]);
                    }
        }
        __syncthreads();
    }

    // ---- epilogue: p = relu(acc*rdinv + b)*dinv; rowmax-quantize to int16 ----
    float dvr[2][2], rdr[2][2];
    #pragma unroll
    for (int mt = 0; mt < 2; ++mt)
        #pragma unroll
        for (int rp = 0; rp < 2; ++rp) {
            int row = rowBase + wm * 32 + mt * 16 + (lane >> 2) + rp * 8;
            bool ok = row < NN;
            dvr[mt][rp] = ok ? g_dinv[row] : 0.f;
            rdr[mt][rp] = ok ? g_rdinv[row] : 0.f;
        }
    float pm[2][2] = {{0.f, 0.f}, {0.f, 0.f}};
    #pragma unroll
    for (int mt = 0; mt < 2; ++mt)
        #pragma unroll
        for (int nj = 0; nj < 4; ++nj) {
            int col = wn * 32 + nj * 8 + (lane & 3) * 2;
            float bz0 = s_bias[col], bz1 = s_bias[col + 1];
            #pragma unroll
            for (int rp = 0; rp < 2; ++rp) {
                float rd = rdr[mt][rp], dv = dvr[mt][rp];
                float p0 = fmaxf(fmaf(acc[mt][nj][rp * 2 + 0], rd, bz0), 0.f) * dv;
                float p1 = fmaxf(fmaf(acc[mt][nj][rp * 2 + 1], rd, bz1), 0.f) * dv;
                pm[mt][rp] = fmaxf(pm[mt][rp], fmaxf(p0, p1));
            }
        }
    #pragma unroll
    for (int mt = 0; mt < 2; ++mt)
        #pragma unroll
        for (int rp = 0; rp < 2; ++rp) {
            float m = pm[mt][rp];
            m = fmaxf(m, __shfl_xor_sync(0xffffffffu, m, 1));
            m = fmaxf(m, __shfl_xor_sync(0xffffffffu, m, 2));
            if ((lane & 3) == 0)
                s_rmax[wm * 32 + mt * 16 + rp * 8 + (lane >> 2)][wn] = m;
        }
    __syncthreads();
    #pragma unroll
    for (int mt = 0; mt < 2; ++mt)
        #pragma unroll
        for (int rp = 0; rp < 2; ++rp) {
            int rl = wm * 32 + mt * 16 + rp * 8 + (lane >> 2);
            int row = rowBase + rl;
            float rm = fmaxf(fmaxf(s_rmax[rl][0], s_rmax[rl][1]),
                             fmaxf(s_rmax[rl][2], s_rmax[rl][3]));
            float sinv = (rm > 0.f) ? (32766.f / rm) : 0.f;
            if (wn == 0 && (lane & 3) == 0 && row < NN)
                outs[row] = rm * (1.f / 32766.f);
            if (row < NN) {
                float rd = rdr[mt][rp], dv = dvr[mt][rp];
                #pragma unroll
                for (int nj = 0; nj < 4; ++nj) {
                    int col = wn * 32 + nj * 8 + (lane & 3) * 2;
                    float bz0 = s_bias[col], bz1 = s_bias[col + 1];
                    float p0 = fmaxf(fmaf(acc[mt][nj][rp * 2 + 0], rd, bz0), 0.f) * dv;
                    float p1 = fmaxf(fmaf(acc[mt][nj][rp * 2 + 1], rd, bz1), 0.f) * dv;
                    *(uint32_t*)(outq + (size_t)row * FH + col) = packs16(p0, p1, sinv);
                }
            }
        }
}

// ======================= SIMT GEMM for final layer (CO=40) =======================
// bases reconstructed from int16 planes: x = q * s_row * rdinv.
template <int CO, int TM, int TN>
__global__ void k_gemm_simt(
    const unsigned short* __restrict__ X0q, const float* __restrict__ X0s,
    const unsigned short* __restrict__ X1q, const float* __restrict__ X1s,
    const unsigned short* __restrict__ X2q, const float* __restrict__ X2s,
    const float* __restrict__ W, const float* __restrict__ bias,
    float* __restrict__ out) {
    constexpr int BM = 128, BK = 16;
    constexpr int NTX = CO / TN;
    constexpr int NTY = BM / TM;
    constexpr int NT = NTX * NTY;
    __shared__ float As[BK][BM + 1];
    __shared__ float Bs[BK][CO];
    const int tid = threadIdx.x;
    const int tx = tid % NTX;
    const int ty = tid / NTX;
    const int rowBase = blockIdx.x * BM;

    float acc[TM][TN];
    #pragma unroll
    for (int m = 0; m < TM; ++m)
        #pragma unroll
        for (int n = 0; n < TN; ++n) acc[m][n] = 0.f;

    #pragma unroll 1
    for (int kt = 0; kt < 24; ++kt) {
        const unsigned short* __restrict__ Xq = (kt < 8) ? X0q : ((kt < 16) ? X1q : X2q);
        const float* __restrict__ Xs = (kt < 8) ? X0s : ((kt < 16) ? X1s : X2s);
        const int kcol = (kt & 7) * BK;
        for (int i = tid; i < BM * BK; i += NT) {
            int r = i >> 4, k = i & 15;
            int row = rowBase + r;
            float v = 0.f;
            if (row < NN) {
                size_t off = (size_t)row * FH + kcol + k;
                v = (float)(short)Xq[off] * Xs[row] * g_rdinv[row];
            }
            As[k][r] = v;
        }
        for (int i = tid; i < BK * CO; i += NT) {
            int k = i / CO, c = i % CO;
            Bs[k][c] = W[(size_t)(kt * BK + k) * CO + c];
        }
        __syncthreads();
        #pragma unroll
        for (int k = 0; k < BK; ++k) {
            float ra[TM], rb[TN];
            #pragma unroll
            for (int m = 0; m < TM; ++m) ra[m] = As[k][ty * TM + m];
            #pragma unroll
            for (int n = 0; n < TN; ++n) rb[n] = Bs[k][tx * TN + n];
            #pragma unroll
            for (int m = 0; m < TM; ++m)
                #pragma unroll
                for (int n = 0; n < TN; ++n)
                    acc[m][n] = fmaf(ra[m], rb[n], acc[m][n]);
        }
        __syncthreads();
    }
    #pragma unroll
    for (int m = 0; m < TM; ++m) {
        int row = rowBase + ty * TM + m;
        if (row < NN) {
            #pragma unroll
            for (int n = 0; n < TN; ++n) {
                int c = tx * TN + n;
                out[(size_t)row * CO + c] = fmaxf(acc[m][n] + bias[c], 0.f);
            }
        }
    }
}

// ======================= host launcher =======================
extern "C" void kernel_launch(void* const* d_in, const int* in_sizes, int n_in,
                              void* d_out, int out_size) {
    const float* feat = (const float*)d_in[0];
    const int*   src  = (const int*)d_in[1];
    const int*   dst  = (const int*)d_in[2];
    const float* W0   = (const float*)d_in[3];
    const float* b0   = (const float*)d_in[4];
    const float* Wh   = (const float*)d_in[5];
    const float* bh   = (const float*)d_in[6];
    const float* Wl   = (const float*)d_in[7];
    const float* bl   = (const float*)d_in[8];
    float* out = (float*)d_out;

    unsigned short *I0, *I1, *I2;
    float *S0, *S1, *S2;
    __nv_bfloat16 *Wth, *Wtl;
    int* degp;
    cudaGetSymbolAddress((void**)&I0,  g_I0);
    cudaGetSymbolAddress((void**)&I1,  g_I1);
    cudaGetSymbolAddress((void**)&I2,  g_I2);
    cudaGetSymbolAddress((void**)&S0,  g_S0);
    cudaGetSymbolAddress((void**)&S1,  g_S1);
    cudaGetSymbolAddress((void**)&S2,  g_S2);
    cudaGetSymbolAddress((void**)&Wth, g_Wth);
    cudaGetSymbolAddress((void**)&Wtl, g_Wtl);
    cudaGetSymbolAddress((void**)&degp, g_deg);

    cudaFuncSetAttribute(k_gemm_mma, cudaFuncAttributeMaxDynamicSharedMemorySize,
                         GM_SMEM_SZ + 1024);

    const int TPB = 256;
    const int nodeBlocks = (NN + TPB - 1) / TPB;
    const int edgeBlocks = (NE + TPB - 1) / TPB;
    const int scanBlocks = (NN + 1023) / 1024;   // 98

    // preprocessing
    cudaMemsetAsync(degp, 0, NN * sizeof(int));
    k_hist<<<edgeBlocks, TPB>>>(dst);
    k_scanA<<<scanBlocks, 1024>>>();
    k_scanB<<<1, 128>>>(scanBlocks);
    k_scanC<<<nodeBlocks, TPB>>>();   // + dinv/rdinv
    k_scatter<<<edgeBlocks, TPB>>>(src, dst);

    // input conversion (warp per row)
    k_featsplit<<<(NN * 32 + TPB - 1) / TPB, TPB>>>(feat);
    k_prep_w<<<(6 * 384 * 128 + TPB - 1) / TPB, TPB>>>(W0, Wh);

    const size_t SL = (size_t)NN * FH;
    const int spmmBlocks = (NN * 32 + TPB - 1) / TPB;
    const int tileBlocks = (NN + 127) / 128;

    int cur = 0;
    for (int l = 0; l < 7; ++l) {
        const unsigned short* I0c = I0 + (size_t)cur * SL;
        const float* S0c = S0 + (size_t)cur * NN;
        k_spmm<1><<<spmmBlocks, TPB>>>(I0c, S0c, nullptr, nullptr, I1, S1);
        k_spmm<2><<<spmmBlocks, TPB>>>(I1, S1, I0c, S0c, I2, S2);
        if (l < 6) {
            const float* bias = (l == 0) ? b0 : (bh + (size_t)(l - 1) * 128);
            int nxt = 1 - cur;
            k_gemm_mma<<<tileBlocks, 512, GM_SMEM_SZ + 1024>>>(
                I0c, S0c, bias,
                Wth + (size_t)l * 128 * 384, Wtl + (size_t)l * 128 * 384,
                I0 + (size_t)nxt * SL, S0 + (size_t)nxt * NN);
            cur = nxt;
        } else {
            k_gemm_simt<FO, 8, 5><<<tileBlocks, 128>>>(
                I0c, S0c, I1, S1, I2, S2, Wl, bl, out);
        }
    }
}